// round 10
// baseline (speedup 1.0000x reference)
#include <cuda_runtime.h>
#include <cuda_bf16.h>
#include <cuda_fp16.h>
#include <cstdint>

#define N_NODES 100000
#define N_EDGES 1600000
#define D_IN    256
#define D_OUT   64
#define BN_EPS  1e-5f
#define CAP     80      // per-node adjacency capacity (Poisson(16): P(deg>=80)<1e-30)

// Scratch (device globals — no allocation allowed)
__device__ __half2 g_yh[(size_t)N_NODES * 32];     // x W^T as half2 (64 cols)
__device__ int     g_cnt[N_NODES];                 // degree / fill cursor
__device__ float   g_dinv[N_NODES];
__device__ int     g_adj[(size_t)N_NODES * CAP];   // bucketed adjacency

// ---------------------------------------------------------------------------
// CSR-free adjacency build: one edge pass into fixed-capacity buckets.
// ---------------------------------------------------------------------------
__global__ __launch_bounds__(256) void k_fill4(const int4* __restrict__ rows4,
                                               const int4* __restrict__ cols4) {
    int i = blockIdx.x * blockDim.x + threadIdx.x;
    if (i < N_EDGES / 4) {
        int4 r = rows4[i];
        int4 c = cols4[i];
        int p0 = atomicAdd(&g_cnt[c.x], 1);
        int p1 = atomicAdd(&g_cnt[c.y], 1);
        int p2 = atomicAdd(&g_cnt[c.z], 1);
        int p3 = atomicAdd(&g_cnt[c.w], 1);
        g_adj[(size_t)c.x * CAP + p0] = r.x;
        g_adj[(size_t)c.y * CAP + p1] = r.y;
        g_adj[(size_t)c.z * CAP + p2] = r.z;
        g_adj[(size_t)c.w * CAP + p3] = r.w;
    }
}
__global__ void k_dinv() {
    int i = blockIdx.x * blockDim.x + threadIdx.x;
    if (i < N_NODES) g_dinv[i] = rsqrtf((float)(g_cnt[i] + 1));   // +1 self-loop
}

// ---------------------------------------------------------------------------
// Tensor-core GEMM via mma.sync, software-pipelined. y = x W^T (unscaled),
// split-bf16 (hi*hi + hi*lo + lo*hi), fp32 accum, half2 store.
// CTA: 128 nodes x 64 douts, 256 threads.
// ---------------------------------------------------------------------------
#define ROWB 144
static constexpr int SM_XHI = 0;
static constexpr int SM_XLO = SM_XHI + 128 * ROWB;
static constexpr int SM_WHI = SM_XLO + 128 * ROWB;
static constexpr int SM_WLO = SM_WHI + 64 * ROWB;
static constexpr int SM_TOTAL = SM_WLO + 64 * ROWB;  // 55296

__device__ __forceinline__ void mma_bf16(float* c, const uint32_t* a,
                                         uint32_t b0, uint32_t b1) {
    asm volatile(
        "mma.sync.aligned.m16n8k16.row.col.f32.bf16.bf16.f32 "
        "{%0,%1,%2,%3}, {%4,%5,%6,%7}, {%8,%9}, {%0,%1,%2,%3};"
        : "+f"(c[0]), "+f"(c[1]), "+f"(c[2]), "+f"(c[3])
        : "r"(a[0]), "r"(a[1]), "r"(a[2]), "r"(a[3]), "r"(b0), "r"(b1));
}
__device__ __forceinline__ uint32_t lds_u32(const char* base, int off) {
    return *(const uint32_t*)(base + off);
}

__device__ __forceinline__ void load_chunk_regs(const float* __restrict__ x,
                                                const float* __restrict__ Wp,
                                                int nodeBase, int kc, int tid,
                                                float4* xv, float4* wv) {
    #pragma unroll
    for (int i = 0; i < 8; i++) {
        int idx = tid + 256 * i;
        int row = idx >> 4, g = idx & 15;
        int node = nodeBase + row;
        xv[i] = (node < N_NODES)
              ? *(const float4*)&x[(size_t)node * D_IN + kc + g * 4]
              : make_float4(0.f, 0.f, 0.f, 0.f);
    }
    #pragma unroll
    for (int i = 0; i < 4; i++) {
        int idx = tid + 256 * i;
        int row = idx >> 4, g = idx & 15;
        wv[i] = *(const float4*)&Wp[(size_t)row * D_IN + kc + g * 4];
    }
}

__device__ __forceinline__ void store_chunk_smem(char* sm, int tid,
                                                 const float4* xv, const float4* wv) {
    #pragma unroll
    for (int i = 0; i < 8; i++) {
        int idx = tid + 256 * i;
        int row = idx >> 4, g = idx & 15;
        float f[4] = {xv[i].x, xv[i].y, xv[i].z, xv[i].w};
        __nv_bfloat16 hi[4], lo[4];
        #pragma unroll
        for (int j = 0; j < 4; j++) {
            hi[j] = __float2bfloat16(f[j]);
            lo[j] = __float2bfloat16(f[j] - __bfloat162float(hi[j]));
        }
        int off = row * ROWB + g * 8;
        *(uint2*)(sm + SM_XHI + off) = *(uint2*)hi;
        *(uint2*)(sm + SM_XLO + off) = *(uint2*)lo;
    }
    #pragma unroll
    for (int i = 0; i < 4; i++) {
        int idx = tid + 256 * i;
        int row = idx >> 4, g = idx & 15;
        float f[4] = {wv[i].x, wv[i].y, wv[i].z, wv[i].w};
        __nv_bfloat16 hi[4], lo[4];
        #pragma unroll
        for (int j = 0; j < 4; j++) {
            hi[j] = __float2bfloat16(f[j]);
            lo[j] = __float2bfloat16(f[j] - __bfloat162float(hi[j]));
        }
        int off = row * ROWB + g * 8;
        *(uint2*)(sm + SM_WHI + off) = *(uint2*)hi;
        *(uint2*)(sm + SM_WLO + off) = *(uint2*)lo;
    }
}

__global__ __launch_bounds__(256) void k_gemm_mma(const float* __restrict__ x,
                                                  const float* __restrict__ Wp) {
    extern __shared__ char sm[];
    const int tid = threadIdx.x;
    const int w   = tid >> 5;
    const int lane = tid & 31;
    const int nodeBase = blockIdx.x * 128;

    float acc[8][4];
    #pragma unroll
    for (int nt = 0; nt < 8; nt++)
        #pragma unroll
        for (int j = 0; j < 4; j++) acc[nt][j] = 0.f;

    float4 xv[8], wv[4];
    load_chunk_regs(x, Wp, nodeBase, 0, tid, xv, wv);
    store_chunk_smem(sm, tid, xv, wv);
    __syncthreads();

    for (int c = 0; c < 4; c++) {
        if (c < 3) load_chunk_regs(x, Wp, nodeBase, (c + 1) * 64, tid, xv, wv);

        #pragma unroll
        for (int ks = 0; ks < 4; ks++) {
            const int kb = ks * 32 + (lane & 3) * 4;
            const int ar = (w * 16 + (lane >> 2)) * ROWB;
            uint32_t ah[4], al[4];
            ah[0] = lds_u32(sm + SM_XHI, ar + kb);
            ah[1] = lds_u32(sm + SM_XHI, ar + 8 * ROWB + kb);
            ah[2] = lds_u32(sm + SM_XHI, ar + kb + 16);
            ah[3] = lds_u32(sm + SM_XHI, ar + 8 * ROWB + kb + 16);
            al[0] = lds_u32(sm + SM_XLO, ar + kb);
            al[1] = lds_u32(sm + SM_XLO, ar + 8 * ROWB + kb);
            al[2] = lds_u32(sm + SM_XLO, ar + kb + 16);
            al[3] = lds_u32(sm + SM_XLO, ar + 8 * ROWB + kb + 16);

            #pragma unroll
            for (int nt = 0; nt < 8; nt++) {
                const int br = (nt * 8 + (lane >> 2)) * ROWB;
                uint32_t bh0 = lds_u32(sm + SM_WHI, br + kb);
                uint32_t bh1 = lds_u32(sm + SM_WHI, br + kb + 16);
                uint32_t bl0 = lds_u32(sm + SM_WLO, br + kb);
                uint32_t bl1 = lds_u32(sm + SM_WLO, br + kb + 16);
                mma_bf16(acc[nt], ah, bh0, bh1);
                mma_bf16(acc[nt], ah, bl0, bl1);
                mma_bf16(acc[nt], al, bh0, bh1);
            }
        }
        __syncthreads();
        if (c < 3) {
            store_chunk_smem(sm, tid, xv, wv);
            __syncthreads();
        }
    }

    // store as half2: col pair (nt*8 + (lane&3)*2, +1) -> index nt*4 + (lane&3)
    const int r0 = nodeBase + w * 16 + (lane >> 2);
    const int r1 = r0 + 8;
    #pragma unroll
    for (int nt = 0; nt < 8; nt++) {
        const int pj = nt * 4 + (lane & 3);
        if (r0 < N_NODES)
            g_yh[(size_t)r0 * 32 + pj] = __floats2half2_rn(acc[nt][0], acc[nt][1]);
        if (r1 < N_NODES)
            g_yh[(size_t)r1 * 32 + pj] = __floats2half2_rn(acc[nt][2], acc[nt][3]);
    }
}

// ---------------------------------------------------------------------------
// Gather: one warp per node, half2 rows (128B/neighbor = 1 sector per warp).
// acc = dinv[n]*y[n] + sum_r dinv[r]*y[r]; epilogue fused.
// ---------------------------------------------------------------------------
__global__ __launch_bounds__(256) void k_gather(const float* __restrict__ bias,
                                                const float* __restrict__ gamma,
                                                const float* __restrict__ beta,
                                                const float* __restrict__ mean,
                                                const float* __restrict__ var,
                                                float* __restrict__ out) {
    const int warp = (blockIdx.x * blockDim.x + threadIdx.x) >> 5;
    const int lane = threadIdx.x & 31;
    if (warp >= N_NODES) return;
    const int node = warp;
    const int c0 = lane * 2;

    const int deg = g_cnt[node];
    const float di = g_dinv[node];
    const long long s = (long long)node * CAP;

    float2 sv = __half22float2(g_yh[(size_t)node * 32 + lane]);
    float2 acc = make_float2(sv.x * di, sv.y * di);   // self-loop term

    for (int base = 0; base < deg; base += 32) {
        int r = 0;
        float dr = 0.f;
        if (base + lane < deg) {
            r = g_adj[s + base + lane];
            dr = g_dinv[r];
        }
        const int cnt = min(32, deg - base);
        int j = 0;
        for (; j + 8 <= cnt; j += 8) {
            float ax = 0.f, ay = 0.f;
            #pragma unroll
            for (int u = 0; u < 8; u++) {
                int rr = __shfl_sync(0xffffffffu, r, j + u);
                float dd = __shfl_sync(0xffffffffu, dr, j + u);
                float2 v = __half22float2(g_yh[(size_t)rr * 32 + lane]);
                ax += dd * v.x;
                ay += dd * v.y;
            }
            acc.x += ax;
            acc.y += ay;
        }
        for (; j < cnt; j++) {
            int rr = __shfl_sync(0xffffffffu, r, j);
            float dd = __shfl_sync(0xffffffffu, dr, j);
            float2 v = __half22float2(g_yh[(size_t)rr * 32 + lane]);
            acc.x += dd * v.x;
            acc.y += dd * v.y;
        }
    }

    float sc0 = rsqrtf(var[c0] + BN_EPS) * gamma[c0];
    float sc1 = rsqrtf(var[c0 + 1] + BN_EPS) * gamma[c0 + 1];
    float2 o;
    o.x = fmaxf((acc.x * di + bias[c0]     - mean[c0])     * sc0 + beta[c0],     0.f);
    o.y = fmaxf((acc.y * di + bias[c0 + 1] - mean[c0 + 1]) * sc1 + beta[c0 + 1], 0.f);
    *(float2*)&out[(size_t)node * D_OUT + c0] = o;
}

// ---------------------------------------------------------------------------
extern "C" void kernel_launch(void* const* d_in, const int* in_sizes, int n_in,
                              void* d_out, int out_size) {
    const float* x     = (const float*)d_in[0];
    const int*   ei    = (const int*)  d_in[1];
    const float* W     = (const float*)d_in[2];
    const float* bias  = (const float*)d_in[3];
    const float* gamma = (const float*)d_in[4];
    const float* beta  = (const float*)d_in[5];
    const float* mean  = (const float*)d_in[6];
    const float* var   = (const float*)d_in[7];
    float* out = (float*)d_out;

    const int4* rows4 = (const int4*)ei;              // edge_index[0] = source
    const int4* cols4 = (const int4*)(ei + N_EDGES);  // edge_index[1] = target

    static cudaStream_t s2 = nullptr;
    static cudaEvent_t evFork = nullptr, evJoin = nullptr;
    static void* cnt_addr = nullptr;
    if (!s2) {
        cudaStreamCreateWithFlags(&s2, cudaStreamNonBlocking);
        cudaEventCreateWithFlags(&evFork, cudaEventDisableTiming);
        cudaEventCreateWithFlags(&evJoin, cudaEventDisableTiming);
        cudaGetSymbolAddress(&cnt_addr, g_cnt);
        cudaFuncSetAttribute(k_gemm_mma, cudaFuncAttributeMaxDynamicSharedMemorySize, SM_TOTAL);
    }

    // fork: adjacency build on s2, GEMM on the capture (default) stream
    cudaEventRecord(evFork, 0);
    cudaStreamWaitEvent(s2, evFork, 0);

    cudaMemsetAsync(cnt_addr, 0, N_NODES * sizeof(int), s2);
    k_fill4<<<(N_EDGES / 4 + 255) / 256, 256, 0, s2>>>(rows4, cols4);
    k_dinv <<<(N_NODES + 255) / 256, 256, 0, s2>>>();

    k_gemm_mma<<<(N_NODES + 127) / 128, 256, SM_TOTAL>>>(x, W);

    // join
    cudaEventRecord(evJoin, s2);
    cudaStreamWaitEvent(0, evJoin, 0);

    k_gather<<<(N_NODES * 32 + 255) / 256, 256>>>(bias, gamma, beta, mean, var, out);
}